// round 2
// baseline (speedup 1.0000x reference)
#include <cuda_runtime.h>

// ---------------- problem constants ----------------
#define BATCH 32
#define HIN   256
#define WIN   256
#define H1    128
#define W1P   128
#define C1    32
#define H2    64
#define W2P   64
#define C2    64
#define FLAT  262144            // 64*64*64
#define NJ    128
#define NCHUNK 512              // split-K chunks for FC1
#define KC     512              // K per chunk (512*512 = 262144)

// ---------------- scratch (static device globals; no runtime alloc) ----------------
__device__ float g_conv1[(size_t)BATCH * H1 * W1P * C1];     // 67 MB
__device__ float g_conv2[(size_t)BATCH * FLAT];              // 33.5 MB
__device__ float g_part[(size_t)NCHUNK * BATCH * NJ];        // 8 MB
__device__ float g_xfc[BATCH * NJ];
__device__ float g_theta[BATCH * 6];

// ---------------- packed fp32x2 helpers (bit-exact 2x fp32 FMA) ----------------
__device__ __forceinline__ unsigned long long pack2(float lo, float hi) {
    unsigned long long r;
    asm("mov.b64 %0, {%1,%2};" : "=l"(r) : "f"(lo), "f"(hi));
    return r;
}
__device__ __forceinline__ void unpack2(unsigned long long v, float& lo, float& hi) {
    asm("mov.b64 {%0,%1}, %2;" : "=f"(lo), "=f"(hi) : "l"(v));
}
__device__ __forceinline__ unsigned long long ffma2(unsigned long long a,
                                                    unsigned long long b,
                                                    unsigned long long c) {
    unsigned long long d;
    asm("fma.rn.f32x2 %0, %1, %2, %3;" : "=l"(d) : "l"(a), "l"(b), "l"(c));
    return d;
}

// =====================================================================
// conv1: [32,256,256,3] -> [32,128,128,32], 3x3 stride2 SAME (pad lo=0, hi=1), relu
// One thread per output pixel, all 32 output channels (16 f32x2 accumulators).
// =====================================================================
__global__ __launch_bounds__(256) void conv1_kernel(const float* __restrict__ in,
                                                    const float* __restrict__ k1,
                                                    const float* __restrict__ b1) {
    __shared__ __align__(16) float wS[864];          // 3*3*3*32
    int tid = threadIdx.x;
    for (int i = tid; i < 864; i += 256) wS[i] = k1[i];
    __syncthreads();

    int pid = blockIdx.x * 256 + tid;                 // < 32*128*128
    int b   = pid >> 14;
    int rem = pid & 16383;
    int oh  = rem >> 7;
    int ow  = rem & 127;

    unsigned long long acc[16];
#pragma unroll
    for (int i = 0; i < 16; i++) acc[i] = 0ULL;

#pragma unroll
    for (int r = 0; r < 3; r++) {
        int ih = 2 * oh + r;
        bool okh = (ih < HIN);
#pragma unroll
        for (int s = 0; s < 3; s++) {
            int iw = 2 * ow + s;
            bool ok = okh && (iw < WIN);
            const float* ip = in + ((size_t)(b * HIN + ih) * WIN + iw) * 3;
            float v[3];
            v[0] = ok ? ip[0] : 0.f;
            v[1] = ok ? ip[1] : 0.f;
            v[2] = ok ? ip[2] : 0.f;
#pragma unroll
            for (int ci = 0; ci < 3; ci++) {
                unsigned long long vv = pack2(v[ci], v[ci]);
                const ulonglong2* wp =
                    (const ulonglong2*)&wS[((r * 3 + s) * 3 + ci) * 32];
#pragma unroll
                for (int p = 0; p < 8; p++) {
                    ulonglong2 wq = wp[p];
                    acc[p * 2 + 0] = ffma2(vv, wq.x, acc[p * 2 + 0]);
                    acc[p * 2 + 1] = ffma2(vv, wq.y, acc[p * 2 + 1]);
                }
            }
        }
    }

    float* op = g_conv1 + ((size_t)(b * H1 + oh) * W1P + ow) * C1;
#pragma unroll
    for (int i = 0; i < 16; i++) {
        float a0, a1;
        unpack2(acc[i], a0, a1);
        float2 st;
        st.x = fmaxf(a0 + b1[2 * i + 0], 0.f);
        st.y = fmaxf(a1 + b1[2 * i + 1], 0.f);
        *(float2*)(op + 2 * i) = st;
    }
}

// =====================================================================
// conv2: [32,128,128,32] -> [32,64,64,64], 3x3 stride2 SAME, relu
// Block tile: 8(oh) x 16(ow) pixels, all 64 channels. Weights (72KB) +
// padded input tile (74KB) in dynamic smem. Thread: 4 pixels x 8 channels
// = 16 f32x2 accumulators.
// =====================================================================
#define IN2_RS 1089   /* 33*33 padded row stride  */
#define IN2_CS 33     /* padded channel stride     */
#define SM2_W  18432  /* 3*3*32*64 weight floats   */
#define SM2_I  18513  /* 17*33*33 input floats     */
#define SM2_BYTES ((SM2_W + SM2_I) * 4)

__global__ __launch_bounds__(256, 1) void conv2_kernel(const float* __restrict__ k2,
                                                       const float* __restrict__ b2) {
    extern __shared__ __align__(16) float sm[];
    float* wS  = sm;
    float* inS = sm + SM2_W;

    int tid = threadIdx.x;
    int b   = blockIdx.z;
    int oh0 = blockIdx.y * 8;
    int ow0 = blockIdx.x * 16;
    int ih0 = oh0 * 2, iw0 = ow0 * 2;

    for (int i = tid; i < SM2_W; i += 256) wS[i] = k2[i];
    for (int i = tid; i < 17 * 33 * 32; i += 256) {
        int ci   = i & 31;
        int rest = i >> 5;
        int cc   = rest % 33;
        int rr   = rest / 33;
        int ih = ih0 + rr, iw = iw0 + cc;
        float v = 0.f;
        if (ih < H1 && iw < W1P)
            v = g_conv1[((size_t)(b * H1 + ih) * W1P + iw) * C1 + ci];
        inS[rr * IN2_RS + cc * IN2_CS + ci] = v;
    }
    __syncthreads();

    int ps = tid >> 3;          // 0..31 pixel set (4 pixels each)
    int cg = tid & 7;           // channel group: channels cg*8 .. cg*8+7

    int base[4];
#pragma unroll
    for (int q = 0; q < 4; q++) {
        int lp = ps * 4 + q;
        int ly = lp >> 4, lx = lp & 15;
        base[q] = ly * 2 * IN2_RS + lx * 2 * IN2_CS;
    }

    unsigned long long acc[16];
#pragma unroll
    for (int i = 0; i < 16; i++) acc[i] = 0ULL;

#pragma unroll
    for (int r = 0; r < 3; r++)
#pragma unroll
        for (int s = 0; s < 3; s++) {
            const float* wrow = wS + ((r * 3 + s) * 32) * 64 + cg * 8;
            int ioff = r * IN2_RS + s * IN2_CS;
#pragma unroll 4
            for (int ci = 0; ci < 32; ci++) {
                ulonglong2 wA = *(const ulonglong2*)(wrow + ci * 64);
                ulonglong2 wB = *(const ulonglong2*)(wrow + ci * 64 + 4);
#pragma unroll
                for (int q = 0; q < 4; q++) {
                    float v = inS[base[q] + ioff + ci];
                    unsigned long long vv = pack2(v, v);
                    acc[q * 4 + 0] = ffma2(vv, wA.x, acc[q * 4 + 0]);
                    acc[q * 4 + 1] = ffma2(vv, wA.y, acc[q * 4 + 1]);
                    acc[q * 4 + 2] = ffma2(vv, wB.x, acc[q * 4 + 2]);
                    acc[q * 4 + 3] = ffma2(vv, wB.y, acc[q * 4 + 3]);
                }
            }
        }

#pragma unroll
    for (int q = 0; q < 4; q++) {
        int lp = ps * 4 + q;
        int ly = lp >> 4, lx = lp & 15;
        float* op = g_conv2 +
                    ((size_t)(b * H2 + oh0 + ly) * W2P + (ow0 + lx)) * C2 + cg * 8;
#pragma unroll
        for (int p = 0; p < 4; p++) {
            float a0, a1;
            unpack2(acc[q * 4 + p], a0, a1);
            float2 st;
            st.x = fmaxf(a0 + b2[cg * 8 + 2 * p + 0], 0.f);
            st.y = fmaxf(a1 + b2[cg * 8 + 2 * p + 1], 0.f);
            *(float2*)(op + 2 * p) = st;
        }
    }
}

// =====================================================================
// FC1 split-K: partial[chunk][b][j] = sum_{k in chunk} x[b,k] * w1[k,j]
// 512 chunks of K=512. Block: 256 threads, each owns 4 batches x 4 j.
// =====================================================================
__global__ __launch_bounds__(256) void fc1_kernel(const float* __restrict__ w1) {
    __shared__ __align__(16) float wS[32 * NJ];   // 16 KB
    __shared__ float xS[32][33];                  // padded, 4.2 KB

    int tid   = threadIdx.x;
    int chunk = blockIdx.x;
    int kbase = chunk * KC;

    int bg = tid >> 5;   // 0..7 -> batches bg*4 .. +3
    int jg = tid & 31;   // 0..31 -> j jg*4 .. +3

    unsigned long long acc[8];
#pragma unroll
    for (int i = 0; i < 8; i++) acc[i] = 0ULL;

    for (int kt = 0; kt < KC / 32; kt++) {
        int k0 = kbase + kt * 32;
        const float4* w1v = (const float4*)(w1 + (size_t)k0 * NJ);
        float4* wSv = (float4*)wS;
        for (int i = tid; i < 1024; i += 256) wSv[i] = w1v[i];
        for (int i = tid; i < 1024; i += 256) {
            int bb = i >> 5, kk = i & 31;
            xS[kk][bb] = g_conv2[(size_t)bb * FLAT + k0 + kk];
        }
        __syncthreads();
#pragma unroll
        for (int kk = 0; kk < 32; kk++) {
            ulonglong2 wv = *(const ulonglong2*)&wS[kk * NJ + jg * 4];
            float x0 = xS[kk][bg * 4 + 0];
            float x1 = xS[kk][bg * 4 + 1];
            float x2 = xS[kk][bg * 4 + 2];
            float x3 = xS[kk][bg * 4 + 3];
            unsigned long long xx;
            xx = pack2(x0, x0); acc[0] = ffma2(xx, wv.x, acc[0]); acc[1] = ffma2(xx, wv.y, acc[1]);
            xx = pack2(x1, x1); acc[2] = ffma2(xx, wv.x, acc[2]); acc[3] = ffma2(xx, wv.y, acc[3]);
            xx = pack2(x2, x2); acc[4] = ffma2(xx, wv.x, acc[4]); acc[5] = ffma2(xx, wv.y, acc[5]);
            xx = pack2(x3, x3); acc[6] = ffma2(xx, wv.x, acc[6]); acc[7] = ffma2(xx, wv.y, acc[7]);
        }
        __syncthreads();
    }

    float* pp = g_part + (size_t)chunk * BATCH * NJ;
#pragma unroll
    for (int bl = 0; bl < 4; bl++) {
        float a0, a1, a2, a3;
        unpack2(acc[bl * 2 + 0], a0, a1);
        unpack2(acc[bl * 2 + 1], a2, a3);
        float4 st = {a0, a1, a2, a3};
        *(float4*)(pp + (bg * 4 + bl) * NJ + jg * 4) = st;
    }
}

// reduce partials + bias + relu -> g_xfc[32*128]
__global__ __launch_bounds__(256) void fc1_reduce_kernel(const float* __restrict__ d1) {
    int idx = blockIdx.x * 256 + threadIdx.x;   // 0..4095
    float s = 0.f;
    for (int c = 0; c < NCHUNK; c++) s += g_part[(size_t)c * (BATCH * NJ) + idx];
    int j = idx & 127;
    g_xfc[idx] = fmaxf(s + d1[j], 0.f);
}

// theta = x @ w2 + d2   (tiny)
__global__ void fc2_kernel(const float* __restrict__ w2, const float* __restrict__ d2) {
    int tid = threadIdx.x;
    if (tid >= BATCH * 6) return;
    int b = tid / 6, i = tid % 6;
    float s = d2[i];
    const float* x = g_xfc + b * NJ;
#pragma unroll 8
    for (int j = 0; j < NJ; j++) s += x[j] * w2[j * 6 + i];
    g_theta[tid] = s;
}

// =====================================================================
// grid_sample: bilinear, zero padding OOB. One thread per output pixel (3 ch).
// =====================================================================
__global__ __launch_bounds__(256) void sample_kernel(const float* __restrict__ in,
                                                     float* __restrict__ out) {
    int pid = blockIdx.x * 256 + threadIdx.x;   // < 32*256*256
    int b   = pid >> 16;
    int rem = pid & 65535;
    int y   = rem >> 8;
    int x   = rem & 255;

    const float* th = g_theta + b * 6;
    float t0 = th[0], t1 = th[1], t2 = th[2];
    float t3 = th[3], t4 = th[4], t5 = th[5];

    float X = (2.f * (float)x + 1.f) * (1.f / 256.f) - 1.f;
    float Y = (2.f * (float)y + 1.f) * (1.f / 256.f) - 1.f;
    float gx = t0 * X + t1 * Y + t2;
    float gy = t3 * X + t4 * Y + t5;
    float px = (gx + 1.f) * 128.f - 0.5f;
    float py = (gy + 1.f) * 128.f - 0.5f;

    float x0f = floorf(px), y0f = floorf(py);
    float wx1 = px - x0f, wx0 = 1.f - wx1;
    float wy1 = py - y0f, wy0 = 1.f - wy1;
    int ix0 = (int)x0f, iy0 = (int)y0f;
    int ix1 = ix0 + 1,  iy1 = iy0 + 1;

    float o0 = 0.f, o1 = 0.f, o2 = 0.f;
    const float* base = in + (size_t)b * HIN * WIN * 3;

    {
        int yi = iy0, xi = ix0; float w = wy0 * wx0;
        if (xi >= 0 && xi < WIN && yi >= 0 && yi < HIN) {
            const float* p = base + ((size_t)yi * WIN + xi) * 3;
            o0 += w * p[0]; o1 += w * p[1]; o2 += w * p[2];
        }
    }
    {
        int yi = iy0, xi = ix1; float w = wy0 * wx1;
        if (xi >= 0 && xi < WIN && yi >= 0 && yi < HIN) {
            const float* p = base + ((size_t)yi * WIN + xi) * 3;
            o0 += w * p[0]; o1 += w * p[1]; o2 += w * p[2];
        }
    }
    {
        int yi = iy1, xi = ix0; float w = wy1 * wx0;
        if (xi >= 0 && xi < WIN && yi >= 0 && yi < HIN) {
            const float* p = base + ((size_t)yi * WIN + xi) * 3;
            o0 += w * p[0]; o1 += w * p[1]; o2 += w * p[2];
        }
    }
    {
        int yi = iy1, xi = ix1; float w = wy1 * wx1;
        if (xi >= 0 && xi < WIN && yi >= 0 && yi < HIN) {
            const float* p = base + ((size_t)yi * WIN + xi) * 3;
            o0 += w * p[0]; o1 += w * p[1]; o2 += w * p[2];
        }
    }

    float* op = out + (size_t)pid * 3;
    op[0] = o0; op[1] = o1; op[2] = o2;
}

// =====================================================================
// launch
// =====================================================================
extern "C" void kernel_launch(void* const* d_in, const int* in_sizes, int n_in,
                              void* d_out, int out_size) {
    const float* inputs = (const float*)d_in[0];
    const float* k1     = (const float*)d_in[1];
    const float* b1     = (const float*)d_in[2];
    const float* k2     = (const float*)d_in[3];
    const float* b2     = (const float*)d_in[4];
    const float* w1     = (const float*)d_in[5];
    const float* d1     = (const float*)d_in[6];
    const float* w2     = (const float*)d_in[7];
    const float* d2     = (const float*)d_in[8];
    float* out = (float*)d_out;

    cudaFuncSetAttribute(conv2_kernel, cudaFuncAttributeMaxDynamicSharedMemorySize,
                         SM2_BYTES);

    conv1_kernel<<<(BATCH * H1 * W1P) / 256, 256>>>(inputs, k1, b1);

    dim3 g2(W2P / 16, H2 / 8, BATCH);   // (4, 8, 32)
    conv2_kernel<<<g2, 256, SM2_BYTES>>>(k2, b2);

    fc1_kernel<<<NCHUNK, 256>>>(w1);
    fc1_reduce_kernel<<<(BATCH * NJ) / 256, 256>>>(d1);
    fc2_kernel<<<1, 192>>>(w2, d2);

    sample_kernel<<<(BATCH * HIN * WIN) / 256, 256>>>(inputs, out);
}